// round 11
// baseline (speedup 1.0000x reference)
#include <cuda_runtime.h>
#include <cuda_bf16.h>
#include <stdint.h>

// ---------------- problem constants ----------------
#define H_DIM 2048
#define I_DIM 4096
#define E_NUM 8
#define T_NUM 4096   // B*S
#define TOPK  2

#define TM 128
#define TK 32
#define NTHREADS 256  // 8 warps, 2m x 4n warp grid
#define RS 80         // SMEM row stride bytes (32 bf16 = 64B + 16B pad)
#define NSTAGE 3

// ---------------- scratch (__device__ globals: allocation-free) ----------------
__device__ int   g_tok[T_NUM * TOPK];
__device__ float g_wgt[T_NUM * TOPK];
__device__ int   g_cnt[E_NUM];
__device__ int   g_off[E_NUM + 1];

#define NW ((size_t)E_NUM * I_DIM * H_DIM)
__device__ __nv_bfloat16 g_xh[(size_t)T_NUM * H_DIM];
__device__ __nv_bfloat16 g_xl[(size_t)T_NUM * H_DIM];
__device__ __nv_bfloat16 g_gh[NW];
__device__ __nv_bfloat16 g_gl[NW];
__device__ __nv_bfloat16 g_uh[NW];
__device__ __nv_bfloat16 g_ul[NW];
__device__ __nv_bfloat16 g_dh[NW];
__device__ __nv_bfloat16 g_dl[NW];
__device__ __nv_bfloat16 g_ih[(size_t)T_NUM * TOPK * I_DIM];
__device__ __nv_bfloat16 g_il[(size_t)T_NUM * TOPK * I_DIM];

// ---------------- helpers ----------------
__device__ __forceinline__ void cpa16(uint32_t dst, const void* src, int srcsz) {
    asm volatile("cp.async.cg.shared.global [%0], [%1], 16, %2;"
                 :: "r"(dst), "l"(src), "r"(srcsz) : "memory");
}
#define CP_COMMIT() asm volatile("cp.async.commit_group;" ::: "memory")
#define CP_WAIT1()  asm volatile("cp.async.wait_group 1;" ::: "memory")
#define CP_WAIT0()  asm volatile("cp.async.wait_group 0;" ::: "memory")

__device__ __forceinline__ uint32_t smem_u32(const void* p) {
    uint32_t a;
    asm("{ .reg .u64 t; cvta.to.shared.u64 t, %1; cvt.u32.u64 %0, t; }" : "=r"(a) : "l"(p));
    return a;
}

#define MMA(d, a, b0, b1) \
    asm volatile("mma.sync.aligned.m16n8k16.row.col.f32.bf16.bf16.f32 " \
        "{%0,%1,%2,%3}, {%4,%5,%6,%7}, {%8,%9}, {%0,%1,%2,%3};" \
        : "+f"((d)[0]), "+f"((d)[1]), "+f"((d)[2]), "+f"((d)[3]) \
        : "r"((a)[0]), "r"((a)[1]), "r"((a)[2]), "r"((a)[3]), "r"(b0), "r"(b1))

#define LDSM4(R, addr) \
    asm volatile("ldmatrix.sync.aligned.m8n8.x4.shared.b16 {%0,%1,%2,%3}, [%4];" \
        : "=r"((R)[0]), "=r"((R)[1]), "=r"((R)[2]), "=r"((R)[3]) : "r"(addr))

__device__ __forceinline__ uint32_t pack2(float v0, float v1, uint32_t& lo_out) {
    __nv_bfloat16 h0 = __float2bfloat16(v0);
    __nv_bfloat16 h1 = __float2bfloat16(v1);
    __nv_bfloat16 l0 = __float2bfloat16(v0 - __bfloat162float(h0));
    __nv_bfloat16 l1 = __float2bfloat16(v1 - __bfloat162float(h1));
    lo_out = (uint32_t)__bfloat16_as_ushort(l0) | ((uint32_t)__bfloat16_as_ushort(l1) << 16);
    return (uint32_t)__bfloat16_as_ushort(h0) | ((uint32_t)__bfloat16_as_ushort(h1) << 16);
}

// ---------------- conversion: fp32 -> (hi,lo) bf16 ----------------
__global__ void __launch_bounds__(256)
convertw_kernel(const float* __restrict__ s0, __nv_bfloat16* __restrict__ h0, __nv_bfloat16* __restrict__ l0,
                const float* __restrict__ s1, __nv_bfloat16* __restrict__ h1, __nv_bfloat16* __restrict__ l1,
                const float* __restrict__ s2, __nv_bfloat16* __restrict__ h2, __nv_bfloat16* __restrict__ l2)
{
    const float* src = (blockIdx.y == 0) ? s0 : (blockIdx.y == 1) ? s1 : s2;
    __nv_bfloat16* hi = (blockIdx.y == 0) ? h0 : (blockIdx.y == 1) ? h1 : h2;
    __nv_bfloat16* lo = (blockIdx.y == 0) ? l0 : (blockIdx.y == 1) ? l1 : l2;
    size_t i = ((size_t)blockIdx.x * 256 + threadIdx.x) * 4;
    float4 v = *(const float4*)(src + i);
    uint32_t a01, a23;
    uint32_t b01 = pack2(v.x, v.y, a01);
    uint32_t b23 = pack2(v.z, v.w, a23);
    *(uint2*)(hi + i) = make_uint2(b01, b23);
    *(uint2*)(lo + i) = make_uint2(a01, a23);
}

__global__ void __launch_bounds__(256)
convert_kernel(const float* __restrict__ src,
               __nv_bfloat16* __restrict__ hi,
               __nv_bfloat16* __restrict__ lo, size_t n)
{
    size_t i = ((size_t)blockIdx.x * 256 + threadIdx.x) * 4;
    if (i >= n) return;
    float4 v = *(const float4*)(src + i);
    uint32_t l01, l23;
    uint32_t h01 = pack2(v.x, v.y, l01);
    uint32_t h23 = pack2(v.z, v.w, l23);
    *(uint2*)(hi + i) = make_uint2(h01, h23);
    *(uint2*)(lo + i) = make_uint2(l01, l23);
}

// ---------------- routing ----------------
__global__ void route_kernel(const unsigned* __restrict__ idx_raw,
                             const float* __restrict__ wts)
{
    __shared__ int s_flag;
    __shared__ int s_cnt[E_NUM];
    __shared__ int s_off[E_NUM + 1];
    const int tid = threadIdx.x, wid = tid >> 5, lane = tid & 31;

    if (tid == 0) s_flag = 0;
    __syncthreads();
    unsigned acc = 0;
    for (int i = 1 + 2 * tid; i < T_NUM * TOPK; i += 512) acc |= idx_raw[i];
    if (acc) atomicOr(&s_flag, 1);
    __syncthreads();
    const int is64 = (s_flag == 0) ? 1 : 0;

    const int e = wid;
    int c = 0;
    for (int base = 0; base < T_NUM; base += 32) {
        int t = base + lane;
        int e0 = is64 ? (int)idx_raw[4 * t]     : (int)idx_raw[2 * t];
        int e1 = is64 ? (int)idx_raw[4 * t + 2] : (int)idx_raw[2 * t + 1];
        c += (e0 == e || e1 == e) ? 1 : 0;
    }
#pragma unroll
    for (int o = 16; o; o >>= 1) c += __shfl_down_sync(0xffffffffu, c, o);
    if (lane == 0) s_cnt[e] = c;
    __syncthreads();
    if (tid == 0) {
        int o = 0;
        for (int i = 0; i < E_NUM; i++) { s_off[i] = o; g_off[i] = o; g_cnt[i] = s_cnt[i]; o += s_cnt[i]; }
        s_off[E_NUM] = o; g_off[E_NUM] = o;
    }
    __syncthreads();
    int p = s_off[e];
    for (int base = 0; base < T_NUM; base += 32) {
        int t = base + lane;
        int e0 = is64 ? (int)idx_raw[4 * t]     : (int)idx_raw[2 * t];
        int e1 = is64 ? (int)idx_raw[4 * t + 2] : (int)idx_raw[2 * t + 1];
        bool m = (e0 == e || e1 == e);
        float w = (e0 == e ? wts[2 * t] : 0.0f) + (e1 == e ? wts[2 * t + 1] : 0.0f);
        unsigned msk = __ballot_sync(0xffffffffu, m);
        int pos = p + __popc(msk & ((1u << lane) - 1u));
        if (m) { g_tok[pos] = t; g_wgt[pos] = w; }
        p += __popc(msk);
    }
}

// ---------------- GEMM1: CTA 128x128, 8 warps, warp tile 64x32 dual-output ----------------
// stage tiles: AH 0, AL 10240, GH 20480, GL 30720, UH 40960, UL 51200
#define ST1 (6 * TM * RS)                 // 61440
#define G1_SMEM (512 + NSTAGE * ST1)      // 184832
#define TN1 128

__global__ void __launch_bounds__(NTHREADS, 1)
gemm1_kernel()
{
    const int e = blockIdx.z;
    const int cnt = g_cnt[e];
    const int rowBase = blockIdx.x * TM;
    if (rowBase >= cnt) return;
    const int off = g_off[e];
    const int n0 = blockIdx.y * TN1;

    extern __shared__ char smem[];
    int* s_tok = (int*)smem;
    const uint32_t sb = smem_u32(smem);

    const int tid = threadIdx.x, wid = tid >> 5, lane = tid & 31;
    const int wm = wid >> 2, wn = wid & 3;       // 2m x 4n; warp tile 64x32
    const int lr = lane >> 2, lc2 = (lane & 3) << 2;
    const int lg = lane >> 3, l7 = lane & 7;

    if (tid < TM) { int r = rowBase + tid; s_tok[tid] = (r < cnt) ? g_tok[off + r] : -1; }
    __syncthreads();

    // staging: thread covers rows rA and rA+64 for each tile, chunk ch
    const int ch = tid & 3, rA = tid >> 2;
    const int selem = ch * 8;
    const uint32_t d0 = sb + 512 + (uint32_t)(rA * RS + ch * 16);
    const uint32_t d1 = d0 + (uint32_t)(64 * RS);
    const int tok0 = s_tok[rA], tok1 = s_tok[rA + 64];
    const int sz0 = (tok0 >= 0) ? 16 : 0, sz1 = (tok1 >= 0) ? 16 : 0;
    const size_t a0 = (size_t)(tok0 >= 0 ? tok0 : 0) * H_DIM + selem;
    const size_t a1 = (size_t)(tok1 >= 0 ? tok1 : 0) * H_DIM + selem;
    const size_t w0 = ((size_t)e * I_DIM + n0 + rA) * H_DIM + selem;
    const size_t w1 = w0 + (size_t)64 * H_DIM;

    const __nv_bfloat16 *xh0 = g_xh + a0, *xl0 = g_xl + a0;
    const __nv_bfloat16 *xh1 = g_xh + a1, *xl1 = g_xl + a1;
    const __nv_bfloat16 *gh0 = g_gh + w0, *gl0 = g_gl + w0, *uh0 = g_uh + w0, *ul0 = g_ul + w0;
    const __nv_bfloat16 *gh1 = g_gh + w1, *gl1 = g_gl + w1, *uh1 = g_uh + w1, *ul1 = g_ul + w1;

    // ldmatrix lane offsets: A m-base = wm*64 (+mt*16), B n-base = wn*32
    const uint32_t aoff = (uint32_t)((wm * 64 + ((lg & 1) << 3) + l7) * RS + ((lg >> 1) << 4));
    const uint32_t boff = (uint32_t)((wn * 32 + ((lg >> 1) << 3) + l7) * RS + ((lg & 1) << 4));

    float accG[4][4][4], accU[4][4][4];
#pragma unroll
    for (int i = 0; i < 4; i++)
#pragma unroll
        for (int j = 0; j < 4; j++)
#pragma unroll
            for (int k = 0; k < 4; k++) { accG[i][j][k] = 0.0f; accU[i][j][k] = 0.0f; }

    const int KB = H_DIM / TK;

#define G1_ISSUE(kb, st) do { \
        uint32_t s_ = (uint32_t)(st) * ST1; \
        int kk_ = (kb) * TK; \
        cpa16(d0 + s_,          xh0 + kk_, sz0); \
        cpa16(d1 + s_,          xh1 + kk_, sz1); \
        cpa16(d0 + s_ + 10240,  xl0 + kk_, sz0); \
        cpa16(d1 + s_ + 10240,  xl1 + kk_, sz1); \
        cpa16(d0 + s_ + 20480,  gh0 + kk_, 16); \
        cpa16(d1 + s_ + 20480,  gh1 + kk_, 16); \
        cpa16(d0 + s_ + 30720,  gl0 + kk_, 16); \
        cpa16(d1 + s_ + 30720,  gl1 + kk_, 16); \
        cpa16(d0 + s_ + 40960,  uh0 + kk_, 16); \
        cpa16(d1 + s_ + 40960,  uh1 + kk_, 16); \
        cpa16(d0 + s_ + 51200,  ul0 + kk_, 16); \
        cpa16(d1 + s_ + 51200,  ul1 + kk_, 16); \
        CP_COMMIT(); \
    } while (0)

    G1_ISSUE(0, 0);
    G1_ISSUE(1, 1);

    for (int kb = 0; kb < KB; kb++) {
        if (kb + 1 < KB) { CP_WAIT1(); } else { CP_WAIT0(); }
        __syncthreads();
        if (kb + 2 < KB) G1_ISSUE(kb + 2, (kb + 2) % NSTAGE);

        const uint32_t s0 = sb + 512 + (uint32_t)((kb % NSTAGE) * ST1);
        const uint32_t sA = s0 + aoff;
        const uint32_t sB = s0 + boff;

#pragma unroll
        for (int k16 = 0; k16 < 2; k16++) {
            const uint32_t ka = (uint32_t)(k16 * 32);
            uint32_t aH[4][4], aL[4][4];
#pragma unroll
            for (int mt = 0; mt < 4; mt++) {
                LDSM4(aH[mt], sA + (uint32_t)(mt * 16 * RS) + ka);
                LDSM4(aL[mt], sA + 10240 + (uint32_t)(mt * 16 * RS) + ka);
            }
#pragma unroll
            for (int nt2 = 0; nt2 < 2; nt2++) {
                const uint32_t bn = sB + (uint32_t)(nt2 * 16 * RS) + ka;
                const int p = nt2 * 2, q = nt2 * 2 + 1;
                uint32_t bg[4], bu[4];
                LDSM4(bg, bn + 20480);      // gate hi
                LDSM4(bu, bn + 40960);      // up hi
                // aH x gate-hi (8 distinct accs)
#pragma unroll
                for (int mt = 0; mt < 4; mt++) {
                    MMA(accG[mt][p], aH[mt], bg[0], bg[1]);
                    MMA(accG[mt][q], aH[mt], bg[2], bg[3]);
                }
                // aH x up-hi
#pragma unroll
                for (int mt = 0; mt < 4; mt++) {
                    MMA(accU[mt][p], aH[mt], bu[0], bu[1]);
                    MMA(accU[mt][q], aH[mt], bu[2], bu[3]);
                }
                // aL x gate-hi
#pragma unroll
                for (int mt = 0; mt < 4; mt++) {
                    MMA(accG[mt][p], aL[mt], bg[0], bg[1]);
                    MMA(accG[mt][q], aL[mt], bg[2], bg[3]);
                }
                // aL x up-hi
#pragma unroll
                for (int mt = 0; mt < 4; mt++) {
                    MMA(accU[mt][p], aL[mt], bu[0], bu[1]);
                    MMA(accU[mt][q], aL[mt], bu[2], bu[3]);
                }
                uint32_t bgl[4], bul[4];
                LDSM4(bgl, bn + 30720);     // gate lo
                LDSM4(bul, bn + 51200);     // up lo
                // aH x gate-lo
#pragma unroll
                for (int mt = 0; mt < 4; mt++) {
                    MMA(accG[mt][p], aH[mt], bgl[0], bgl[1]);
                    MMA(accG[mt][q], aH[mt], bgl[2], bgl[3]);
                }
                // aH x up-lo
#pragma unroll
                for (int mt = 0; mt < 4; mt++) {
                    MMA(accU[mt][p], aH[mt], bul[0], bul[1]);
                    MMA(accU[mt][q], aH[mt], bul[2], bul[3]);
                }
            }
        }
    }
#undef G1_ISSUE

    // epilogue: silu(g)*u -> inter hi/lo
#pragma unroll
    for (int mt = 0; mt < 4; mt++) {
#pragma unroll
        for (int half = 0; half < 2; half++) {
            int rloc = wm * 64 + mt * 16 + lr + half * 8;
            int r = rowBase + rloc;
            if (r >= cnt) continue;
            size_t base = (size_t)(off + r) * I_DIM + n0 + wn * 32 + (lc2 >> 1);
#pragma unroll
            for (int nt = 0; nt < 4; nt++) {
                float g0 = accG[mt][nt][half * 2 + 0], u0 = accU[mt][nt][half * 2 + 0];
                float g1 = accG[mt][nt][half * 2 + 1], u1 = accU[mt][nt][half * 2 + 1];
                float v0 = (g0 / (1.0f + __expf(-g0))) * u0;
                float v1 = (g1 / (1.0f + __expf(-g1))) * u1;
                uint32_t lo;
                uint32_t hi = pack2(v0, v1, lo);
                *(uint32_t*)(g_ih + base + nt * 8) = hi;
                *(uint32_t*)(g_il + base + nt * 8) = lo;
            }
        }
    }
}

// ---------------- GEMM2: CTA 128x256, 8 warps, warp tile 64x64 ----------------
// stage tiles: AH 0 (10240), AL 10240, BH 20480 (20480), BL 40960 (20480)
#define ST2 61440
#define G2_SMEM (1024 + NSTAGE * ST2)     // 185344
#define TN2 256

__global__ void __launch_bounds__(NTHREADS, 1)
gemm2_kernel(float* __restrict__ out)
{
    const int e = blockIdx.z;
    const int cnt = g_cnt[e];
    const int rowBase = blockIdx.x * TM;
    if (rowBase >= cnt) return;
    const int off = g_off[e];
    const int n0 = blockIdx.y * TN2;

    extern __shared__ char smem[];
    int*   s_tok = (int*)smem;
    float* s_wgt = (float*)(smem + 512);
    const uint32_t sb = smem_u32(smem);

    const int tid = threadIdx.x, wid = tid >> 5, lane = tid & 31;
    const int wm = wid >> 2, wn = wid & 3;       // 2m x 4n; warp tile 64x64
    const int lr = lane >> 2, lc2 = (lane & 3) << 2;
    const int lg = lane >> 3, l7 = lane & 7;

    if (tid < TM) {
        int r = rowBase + tid;
        s_tok[tid] = (r < cnt) ? g_tok[off + r] : -1;
        s_wgt[tid] = (r < cnt) ? g_wgt[off + r] : 0.0f;
    }
    __syncthreads();

    const int ch = tid & 3, rA = tid >> 2;
    const int selem = ch * 8;
    const uint32_t d0 = sb + 1024 + (uint32_t)(rA * RS + ch * 16);
    const uint32_t d1 = d0 + (uint32_t)(64 * RS);
    const int v0ok = (rowBase + rA < cnt), v1ok = (rowBase + rA + 64 < cnt);
    const int sz0 = v0ok ? 16 : 0, sz1 = v1ok ? 16 : 0;
    const size_t a0 = (size_t)(off + (v0ok ? rowBase + rA : 0)) * I_DIM + selem;
    const size_t a1 = (size_t)(off + (v1ok ? rowBase + rA + 64 : 0)) * I_DIM + selem;
    const size_t b0r = ((size_t)e * H_DIM + n0 + rA) * I_DIM + selem;

    const __nv_bfloat16 *ih0 = g_ih + a0, *il0 = g_il + a0;
    const __nv_bfloat16 *ih1 = g_ih + a1, *il1 = g_il + a1;
    const __nv_bfloat16 *bh = g_dh + b0r, *bl = g_dl + b0r;   // rows rA+64j via +j*64*I_DIM

    const uint32_t aoff = (uint32_t)((wm * 64 + ((lg & 1) << 3) + l7) * RS + ((lg >> 1) << 4));
    const uint32_t boff = (uint32_t)((wn * 64 + ((lg >> 1) << 3) + l7) * RS + ((lg & 1) << 4));

    float acc[4][8][4];
#pragma unroll
    for (int i = 0; i < 4; i++)
#pragma unroll
        for (int j = 0; j < 8; j++)
#pragma unroll
            for (int k = 0; k < 4; k++) acc[i][j][k] = 0.0f;

    const int KB = I_DIM / TK;

#define G2_ISSUE(kb, st) do { \
        uint32_t s_ = (uint32_t)(st) * ST2; \
        int kk_ = (kb) * TK; \
        cpa16(d0 + s_,         ih0 + kk_, sz0); \
        cpa16(d1 + s_,         ih1 + kk_, sz1); \
        cpa16(d0 + s_ + 10240, il0 + kk_, sz0); \
        cpa16(d1 + s_ + 10240, il1 + kk_, sz1); \
        _Pragma("unroll") \
        for (int j_ = 0; j_ < 4; j_++) { \
            uint32_t bd_ = d0 + s_ + 20480 + (uint32_t)(j_ * 64 * RS); \
            cpa16(bd_,         bh + (size_t)j_ * 64 * I_DIM + kk_, 16); \
            cpa16(bd_ + 20480, bl + (size_t)j_ * 64 * I_DIM + kk_, 16); \
        } \
        CP_COMMIT(); \
    } while (0)

    G2_ISSUE(0, 0);
    G2_ISSUE(1, 1);

    for (int kb = 0; kb < KB; kb++) {
        if (kb + 1 < KB) { CP_WAIT1(); } else { CP_WAIT0(); }
        __syncthreads();
        if (kb + 2 < KB) G2_ISSUE(kb + 2, (kb + 2) % NSTAGE);

        const uint32_t s0 = sb + 1024 + (uint32_t)((kb % NSTAGE) * ST2);
        const uint32_t sA = s0 + aoff;
        const uint32_t sB = s0 + 20480 + boff;

#pragma unroll
        for (int k16 = 0; k16 < 2; k16++) {
            const uint32_t ka = (uint32_t)(k16 * 32);
            uint32_t aH[4][4], aL[4][4];
#pragma unroll
            for (int mt = 0; mt < 4; mt++) {
                LDSM4(aH[mt], sA + (uint32_t)(mt * 16 * RS) + ka);
                LDSM4(aL[mt], sA + 10240 + (uint32_t)(mt * 16 * RS) + ka);
            }
#pragma unroll
            for (int ng = 0; ng < 4; ng++) {
                const uint32_t bn = sB + (uint32_t)(ng * 16 * RS) + ka;
                const int p = ng * 2, q = ng * 2 + 1;
                uint32_t bH[4], bL[4];
                LDSM4(bH, bn);              // down hi
                LDSM4(bL, bn + 20480);      // down lo
                // aH x bH (8 distinct accs)
#pragma unroll
                for (int mt = 0; mt < 4; mt++) {
                    MMA(acc[mt][p], aH[mt], bH[0], bH[1]);
                    MMA(acc[mt][q], aH[mt], bH[2], bH[3]);
                }
                // aL x bH
#pragma unroll
                for (int mt = 0; mt < 4; mt++) {
                    MMA(acc[mt][p], aL[mt], bH[0], bH[1]);
                    MMA(acc[mt][q], aL[mt], bH[2], bH[3]);
                }
                // aH x bL
#pragma unroll
                for (int mt = 0; mt < 4; mt++) {
                    MMA(acc[mt][p], aH[mt], bL[0], bL[1]);
                    MMA(acc[mt][q], aH[mt], bL[2], bL[3]);
                }
            }
        }
    }
#undef G2_ISSUE

    // epilogue: weighted scatter-add
#pragma unroll
    for (int mt = 0; mt < 4; mt++) {
#pragma unroll
        for (int half = 0; half < 2; half++) {
            int rloc = wm * 64 + mt * 16 + lr + half * 8;
            int t = s_tok[rloc];
            if (t < 0) continue;
            float w = s_wgt[rloc];
            float* dst = out + (size_t)t * H_DIM + n0 + wn * 64 + (lc2 >> 1);
#pragma unroll
            for (int nt = 0; nt < 8; nt++) {
                atomicAdd(dst + nt * 8 + 0, w * acc[mt][nt][half * 2 + 0]);
                atomicAdd(dst + nt * 8 + 1, w * acc[mt][nt][half * 2 + 1]);
            }
        }
    }
}

// ---------------- launch ----------------
extern "C" void kernel_launch(void* const* d_in, const int* in_sizes, int n_in,
                              void* d_out, int out_size)
{
    const float*    x    = (const float*)d_in[0];
    const unsigned* idx  = (const unsigned*)d_in[1];
    const float*    wts  = (const float*)d_in[2];
    const float*    gate = (const float*)d_in[3];
    const float*    up   = (const float*)d_in[4];
    const float*    down = (const float*)d_in[5];
    float* out = (float*)d_out;

    static int attr_done = 0;
    if (!attr_done) {
        cudaFuncSetAttribute(gemm1_kernel, cudaFuncAttributeMaxDynamicSharedMemorySize, G1_SMEM);
        cudaFuncSetAttribute(gemm2_kernel, cudaFuncAttributeMaxDynamicSharedMemorySize, G2_SMEM);
        attr_done = 1;
    }

    cudaMemsetAsync(out, 0, (size_t)out_size * sizeof(float));
    route_kernel<<<1, 256>>>(idx, wts);

    __nv_bfloat16 *gh, *gl, *uh, *ul, *dh, *dl, *xh, *xl;
    cudaGetSymbolAddress((void**)&gh, g_gh); cudaGetSymbolAddress((void**)&gl, g_gl);
    cudaGetSymbolAddress((void**)&uh, g_uh); cudaGetSymbolAddress((void**)&ul, g_ul);
    cudaGetSymbolAddress((void**)&dh, g_dh); cudaGetSymbolAddress((void**)&dl, g_dl);
    cudaGetSymbolAddress((void**)&xh, g_xh); cudaGetSymbolAddress((void**)&xl, g_xl);

    const size_t nw = NW;
    const size_t nx = (size_t)T_NUM * H_DIM;
    convertw_kernel<<<dim3((unsigned)(nw / 1024), 3), 256>>>(gate, gh, gl, up, uh, ul, down, dh, dl);
    convert_kernel<<<(unsigned)(nx / 1024), 256>>>(x, xh, xl, nx);

    gemm1_kernel<<<dim3(T_NUM / TM, I_DIM / TN1, E_NUM), NTHREADS, G1_SMEM>>>();
    gemm2_kernel<<<dim3(T_NUM / TM, H_DIM / TN2, E_NUM), NTHREADS, G2_SMEM>>>(out);
}

// round 12
// speedup vs baseline: 1.2841x; 1.2841x over previous
#include <cuda_runtime.h>
#include <stdint.h>

// ---------------- problem constants ----------------
#define H_DIM 2048
#define I_DIM 4096
#define E_NUM 8
#define T_NUM 4096   // B*S
#define TOPK  2

#define TM 128
#define TN 128
#define TK 32        // fp32 K elements per k-block (128B rows)
#define NTHREADS 512
#define RS 144       // SMEM row stride bytes: 32 fp32 = 128B + 16B pad (conflict-free ldmatrix)
#define NSTAGE 3
#define TILE_B (128 * RS)   // 18432 bytes per 128-row tile

// ---------------- scratch (__device__ globals: allocation-free) ----------------
__device__ int   g_tok[T_NUM * TOPK];
__device__ float g_wgt[T_NUM * TOPK];
__device__ int   g_cnt[E_NUM];
__device__ int   g_off[E_NUM + 1];

#define NW ((size_t)E_NUM * I_DIM * H_DIM)
__device__ float g_xw[(size_t)T_NUM * H_DIM];        // x rounded to tf32
__device__ float g_gw[NW];                            // gate rounded
__device__ float g_uw[NW];                            // up rounded
__device__ float g_dw[NW];                            // down rounded
__device__ float g_inter[(size_t)T_NUM * TOPK * I_DIM]; // inter (tf32-rounded fp32)

// ---------------- helpers ----------------
__device__ __forceinline__ void cpa16(uint32_t dst, const void* src, int srcsz) {
    asm volatile("cp.async.cg.shared.global [%0], [%1], 16, %2;"
                 :: "r"(dst), "l"(src), "r"(srcsz) : "memory");
}
#define CP_COMMIT() asm volatile("cp.async.commit_group;" ::: "memory")
#define CP_WAIT1()  asm volatile("cp.async.wait_group 1;" ::: "memory")
#define CP_WAIT0()  asm volatile("cp.async.wait_group 0;" ::: "memory")

__device__ __forceinline__ uint32_t smem_u32(const void* p) {
    uint32_t a;
    asm("{ .reg .u64 t; cvta.to.shared.u64 t, %1; cvt.u32.u64 %0, t; }" : "=r"(a) : "l"(p));
    return a;
}

// tf32 MMA: m16n8k8, A/B raw fp32 bit-patterns in b32 regs
#define MMAT(d, a, b0, b1) \
    asm volatile("mma.sync.aligned.m16n8k8.row.col.f32.tf32.tf32.f32 " \
        "{%0,%1,%2,%3}, {%4,%5,%6,%7}, {%8,%9}, {%0,%1,%2,%3};" \
        : "+f"((d)[0]), "+f"((d)[1]), "+f"((d)[2]), "+f"((d)[3]) \
        : "r"((a)[0]), "r"((a)[1]), "r"((a)[2]), "r"((a)[3]), "r"(b0), "r"(b1))

#define LDSM4(R, addr) \
    asm volatile("ldmatrix.sync.aligned.m8n8.x4.shared.b16 {%0,%1,%2,%3}, [%4];" \
        : "=r"((R)[0]), "=r"((R)[1]), "=r"((R)[2]), "=r"((R)[3]) : "r"(addr))

__device__ __forceinline__ float rna_tf32(float f) {
    uint32_t r;
    asm("cvt.rna.tf32.f32 %0, %1;" : "=r"(r) : "f"(f));
    return __uint_as_float(r);
}

// ---------------- rounding: fp32 -> tf32 (rna) ----------------
__global__ void __launch_bounds__(256)
roundw_kernel(const float* __restrict__ s0, float* __restrict__ d0,
              const float* __restrict__ s1, float* __restrict__ d1,
              const float* __restrict__ s2, float* __restrict__ d2)
{
    const float* src = (blockIdx.y == 0) ? s0 : (blockIdx.y == 1) ? s1 : s2;
    float* dst = (blockIdx.y == 0) ? d0 : (blockIdx.y == 1) ? d1 : d2;
    size_t i = ((size_t)blockIdx.x * 256 + threadIdx.x) * 4;
    float4 v = *(const float4*)(src + i);
    v.x = rna_tf32(v.x); v.y = rna_tf32(v.y); v.z = rna_tf32(v.z); v.w = rna_tf32(v.w);
    *(float4*)(dst + i) = v;
}

__global__ void __launch_bounds__(256)
roundx_kernel(const float* __restrict__ src, float* __restrict__ dst, size_t n)
{
    size_t i = ((size_t)blockIdx.x * 256 + threadIdx.x) * 4;
    if (i >= n) return;
    float4 v = *(const float4*)(src + i);
    v.x = rna_tf32(v.x); v.y = rna_tf32(v.y); v.z = rna_tf32(v.z); v.w = rna_tf32(v.w);
    *(float4*)(dst + i) = v;
}

// ---------------- routing ----------------
__global__ void route_kernel(const unsigned* __restrict__ idx_raw,
                             const float* __restrict__ wts)
{
    __shared__ int s_flag;
    __shared__ int s_cnt[E_NUM];
    __shared__ int s_off[E_NUM + 1];
    const int tid = threadIdx.x, wid = tid >> 5, lane = tid & 31;

    if (tid == 0) s_flag = 0;
    __syncthreads();
    unsigned acc = 0;
    for (int i = 1 + 2 * tid; i < T_NUM * TOPK; i += 512) acc |= idx_raw[i];
    if (acc) atomicOr(&s_flag, 1);
    __syncthreads();
    const int is64 = (s_flag == 0) ? 1 : 0;

    const int e = wid;
    int c = 0;
    for (int base = 0; base < T_NUM; base += 32) {
        int t = base + lane;
        int e0 = is64 ? (int)idx_raw[4 * t]     : (int)idx_raw[2 * t];
        int e1 = is64 ? (int)idx_raw[4 * t + 2] : (int)idx_raw[2 * t + 1];
        c += (e0 == e || e1 == e) ? 1 : 0;
    }
#pragma unroll
    for (int o = 16; o; o >>= 1) c += __shfl_down_sync(0xffffffffu, c, o);
    if (lane == 0) s_cnt[e] = c;
    __syncthreads();
    if (tid == 0) {
        int o = 0;
        for (int i = 0; i < E_NUM; i++) { s_off[i] = o; g_off[i] = o; g_cnt[i] = s_cnt[i]; o += s_cnt[i]; }
        s_off[E_NUM] = o; g_off[E_NUM] = o;
    }
    __syncthreads();
    int p = s_off[e];
    for (int base = 0; base < T_NUM; base += 32) {
        int t = base + lane;
        int e0 = is64 ? (int)idx_raw[4 * t]     : (int)idx_raw[2 * t];
        int e1 = is64 ? (int)idx_raw[4 * t + 2] : (int)idx_raw[2 * t + 1];
        bool m = (e0 == e || e1 == e);
        float w = (e0 == e ? wts[2 * t] : 0.0f) + (e1 == e ? wts[2 * t + 1] : 0.0f);
        unsigned msk = __ballot_sync(0xffffffffu, m);
        int pos = p + __popc(msk & ((1u << lane) - 1u));
        if (m) { g_tok[pos] = t; g_wgt[pos] = w; }
        p += __popc(msk);
    }
}

// ---------------- GEMM1 (tf32): inter = silu(X G^T) * (X U^T) ----------------
// stage: A 0, G TILE_B, U 2*TILE_B; stage size 3*TILE_B = 55296
#define ST1 (3 * TILE_B)
#define G1_SMEM (512 + NSTAGE * ST1)      // 166400

__global__ void __launch_bounds__(NTHREADS, 1)
gemm1_kernel()
{
    const int e = blockIdx.z;
    const int cnt = g_cnt[e];
    const int rowBase = blockIdx.x * TM;
    if (rowBase >= cnt) return;
    const int off = g_off[e];
    const int n0 = blockIdx.y * TN;

    extern __shared__ char smem[];
    int* s_tok = (int*)smem;
    const uint32_t sb = smem_u32(smem);

    const int tid = threadIdx.x, wid = tid >> 5, lane = tid & 31;
    const int wm = wid >> 2, wn = wid & 3;       // 4m x 4n warp grid, warp tile 32x32
    const int lr = lane >> 2, lc = lane & 3;
    const int lg = lane >> 3, l7 = lane & 7;

    if (tid < TM) { int r = rowBase + tid; s_tok[tid] = (r < cnt) ? g_tok[off + r] : -1; }
    __syncthreads();

    // cp.async staging: row = tid>>2 (0..127), two 16B chunks ch2, ch2+1
    const int srow = tid >> 2, ch2 = (tid & 3) * 2;
    const int selem = ch2 * 4;                    // fp32 element offset in row
    const uint32_t d0 = sb + 512 + (uint32_t)(srow * RS + ch2 * 16);
    const int stok = s_tok[srow];
    const int asz = (stok >= 0) ? 16 : 0;
    const float* xsrc = g_xw + (size_t)(stok >= 0 ? stok : 0) * H_DIM + selem;
    const float* gsrc = g_gw + ((size_t)e * I_DIM + n0 + srow) * H_DIM + selem;
    const float* usrc = g_uw + ((size_t)e * I_DIM + n0 + srow) * H_DIM + selem;

    // ldmatrix lane offsets (tf32 fragments):
    // A: row = base_m + (lg&1)*8 + l7, byte = (lg>>1)*16
    const uint32_t aoff = (uint32_t)((wm * 32 + ((lg & 1) << 3) + l7) * RS + ((lg >> 1) << 4));
    // B: row = base_n + (lg>>1)*8 + l7, byte = (lg&1)*16
    const uint32_t boff = (uint32_t)((wn * 32 + ((lg >> 1) << 3) + l7) * RS + ((lg & 1) << 4));

    float accG[2][4][4], accU[2][4][4];
#pragma unroll
    for (int i = 0; i < 2; i++)
#pragma unroll
        for (int j = 0; j < 4; j++)
#pragma unroll
            for (int k = 0; k < 4; k++) { accG[i][j][k] = 0.0f; accU[i][j][k] = 0.0f; }

    const int KB = H_DIM / TK;   // 64

#define G1_ISSUE(kb, st) do { \
        uint32_t b_ = d0 + (uint32_t)(st) * ST1; \
        int kk_ = (kb) * TK; \
        cpa16(b_,                       xsrc + kk_,     asz); \
        cpa16(b_ + 16,                  xsrc + kk_ + 4, asz); \
        cpa16(b_ + TILE_B,              gsrc + kk_,     16); \
        cpa16(b_ + TILE_B + 16,         gsrc + kk_ + 4, 16); \
        cpa16(b_ + 2 * TILE_B,          usrc + kk_,     16); \
        cpa16(b_ + 2 * TILE_B + 16,     usrc + kk_ + 4, 16); \
        CP_COMMIT(); \
    } while (0)

    G1_ISSUE(0, 0);
    G1_ISSUE(1, 1);

    for (int kb = 0; kb < KB; kb++) {
        if (kb + 1 < KB) { CP_WAIT1(); } else { CP_WAIT0(); }
        __syncthreads();
        if (kb + 2 < KB) G1_ISSUE(kb + 2, (kb + 2) % NSTAGE);

        const uint32_t s0 = sb + 512 + (uint32_t)((kb % NSTAGE) * ST1);
        const uint32_t sA = s0 + aoff;
        const uint32_t sG = s0 + TILE_B + boff;
        const uint32_t sU = s0 + 2 * TILE_B + boff;

#pragma unroll
        for (int ks = 0; ks < 4; ks++) {        // 4 x k8 per k-block
            const uint32_t ka = (uint32_t)(ks * 32);
            uint32_t a[2][4];
            LDSM4(a[0], sA + ka);
            LDSM4(a[1], sA + 16 * RS + ka);
#pragma unroll
            for (int np = 0; np < 2; np++) {    // each covers 2 n8 tiles
                const uint32_t bo = (uint32_t)(np * 16 * RS) + ka;
                const int p = np * 2, q = np * 2 + 1;
                uint32_t bg[4], bu[4];
                LDSM4(bg, sG + bo);
                LDSM4(bu, sU + bo);
                MMAT(accG[0][p], a[0], bg[0], bg[1]);
                MMAT(accG[0][q], a[0], bg[2], bg[3]);
                MMAT(accG[1][p], a[1], bg[0], bg[1]);
                MMAT(accG[1][q], a[1], bg[2], bg[3]);
                MMAT(accU[0][p], a[0], bu[0], bu[1]);
                MMAT(accU[0][q], a[0], bu[2], bu[3]);
                MMAT(accU[1][p], a[1], bu[0], bu[1]);
                MMAT(accU[1][q], a[1], bu[2], bu[3]);
            }
        }
    }
#undef G1_ISSUE

    // epilogue: silu(g)*u, rounded to tf32, stored fp32
#pragma unroll
    for (int mt = 0; mt < 2; mt++) {
#pragma unroll
        for (int half = 0; half < 2; half++) {
            int rloc = wm * 32 + mt * 16 + lr + half * 8;
            int r = rowBase + rloc;
            if (r >= cnt) continue;
            float* dst = g_inter + (size_t)(off + r) * I_DIM + n0 + wn * 32 + lc * 2;
#pragma unroll
            for (int nt = 0; nt < 4; nt++) {
                float g0 = accG[mt][nt][half * 2 + 0], u0 = accU[mt][nt][half * 2 + 0];
                float g1 = accG[mt][nt][half * 2 + 1], u1 = accU[mt][nt][half * 2 + 1];
                float v0 = rna_tf32((g0 / (1.0f + __expf(-g0))) * u0);
                float v1 = rna_tf32((g1 / (1.0f + __expf(-g1))) * u1);
                *(float2*)(dst + nt * 8) = make_float2(v0, v1);
            }
        }
    }
}

// ---------------- GEMM2 (tf32): out[tok] += w * (inter D^T) ----------------
// stage: A 0, B TILE_B; stage size 2*TILE_B = 36864
#define ST2 (2 * TILE_B)
#define G2_SMEM (1024 + NSTAGE * ST2)     // 111616

__global__ void __launch_bounds__(NTHREADS, 1)
gemm2_kernel(float* __restrict__ out)
{
    const int e = blockIdx.z;
    const int cnt = g_cnt[e];
    const int rowBase = blockIdx.x * TM;
    if (rowBase >= cnt) return;
    const int off = g_off[e];
    const int n0 = blockIdx.y * TN;

    extern __shared__ char smem[];
    int*   s_tok = (int*)smem;
    float* s_wgt = (float*)(smem + 512);
    const uint32_t sb = smem_u32(smem);

    const int tid = threadIdx.x, wid = tid >> 5, lane = tid & 31;
    const int wm = wid >> 2, wn = wid & 3;
    const int lr = lane >> 2, lc = lane & 3;
    const int lg = lane >> 3, l7 = lane & 7;

    if (tid < TM) {
        int r = rowBase + tid;
        s_tok[tid] = (r < cnt) ? g_tok[off + r] : -1;
        s_wgt[tid] = (r < cnt) ? g_wgt[off + r] : 0.0f;
    }
    __syncthreads();

    const int srow = tid >> 2, ch2 = (tid & 3) * 2;
    const int selem = ch2 * 4;
    const uint32_t d0 = sb + 1024 + (uint32_t)(srow * RS + ch2 * 16);
    const int valid = (rowBase + srow < cnt);
    const int asz = valid ? 16 : 0;
    const float* asrc = g_inter + (size_t)(off + (valid ? rowBase + srow : 0)) * I_DIM + selem;
    const float* bsrc = g_dw + ((size_t)e * H_DIM + n0 + srow) * I_DIM + selem;

    const uint32_t aoff = (uint32_t)((wm * 32 + ((lg & 1) << 3) + l7) * RS + ((lg >> 1) << 4));
    const uint32_t boff = (uint32_t)((wn * 32 + ((lg >> 1) << 3) + l7) * RS + ((lg & 1) << 4));

    float acc[2][4][4];
#pragma unroll
    for (int i = 0; i < 2; i++)
#pragma unroll
        for (int j = 0; j < 4; j++)
#pragma unroll
            for (int k = 0; k < 4; k++) acc[i][j][k] = 0.0f;

    const int KB = I_DIM / TK;   // 128

#define G2_ISSUE(kb, st) do { \
        uint32_t b_ = d0 + (uint32_t)(st) * ST2; \
        int kk_ = (kb) * TK; \
        cpa16(b_,                   asrc + kk_,     asz); \
        cpa16(b_ + 16,              asrc + kk_ + 4, asz); \
        cpa16(b_ + TILE_B,          bsrc + kk_,     16); \
        cpa16(b_ + TILE_B + 16,     bsrc + kk_ + 4, 16); \
        CP_COMMIT(); \
    } while (0)

    G2_ISSUE(0, 0);
    G2_ISSUE(1, 1);

    for (int kb = 0; kb < KB; kb++) {
        if (kb + 1 < KB) { CP_WAIT1(); } else { CP_WAIT0(); }
        __syncthreads();
        if (kb + 2 < KB) G2_ISSUE(kb + 2, (kb + 2) % NSTAGE);

        const uint32_t s0 = sb + 1024 + (uint32_t)((kb % NSTAGE) * ST2);
        const uint32_t sA = s0 + aoff;
        const uint32_t sB = s0 + TILE_B + boff;

#pragma unroll
        for (int ks = 0; ks < 4; ks++) {
            const uint32_t ka = (uint32_t)(ks * 32);
            uint32_t a[2][4];
            LDSM4(a[0], sA + ka);
            LDSM4(a[1], sA + 16 * RS + ka);
#pragma unroll
            for (int np = 0; np < 2; np++) {
                const uint32_t bo = (uint32_t)(np * 16 * RS) + ka;
                const int p = np * 2, q = np * 2 + 1;
                uint32_t b[4];
                LDSM4(b, sB + bo);
                MMAT(acc[0][p], a[0], b[0], b[1]);
                MMAT(acc[0][q], a[0], b[2], b[3]);
                MMAT(acc[1][p], a[1], b[0], b[1]);
                MMAT(acc[1][q], a[1], b[2], b[3]);
            }
        }
    }
#undef G2_ISSUE

    // epilogue: weighted scatter-add
#pragma unroll
    for (int mt = 0; mt < 2; mt++) {
#pragma unroll
        for (int half = 0; half < 2; half++) {
            int rloc = wm * 32 + mt * 16 + lr + half * 8;
            int t = s_tok[rloc];
            if (t < 0) continue;
            float w = s_wgt[rloc];
            float* dst = out + (size_t)t * H_DIM + n0 + wn * 32 + lc * 2;
#pragma unroll
            for (int nt = 0; nt < 4; nt++) {
                atomicAdd(dst + nt * 8 + 0, w * acc[mt][nt][half * 2 + 0]);
                atomicAdd(dst + nt * 8 + 1, w * acc[mt][nt][half * 2 + 1]);
            }
        }
    }
}

// ---------------- launch ----------------
extern "C" void kernel_launch(void* const* d_in, const int* in_sizes, int n_in,
                              void* d_out, int out_size)
{
    const float*    x    = (const float*)d_in[0];
    const unsigned* idx  = (const unsigned*)d_in[1];
    const float*    wts  = (const float*)d_in[2];
    const float*    gate = (const float*)d_in[3];
    const float*    up   = (const float*)d_in[4];
    const float*    down = (const float*)d_in[5];
    float* out = (float*)d_out;

    static int attr_done = 0;
    if (!attr_done) {
        cudaFuncSetAttribute(gemm1_kernel, cudaFuncAttributeMaxDynamicSharedMemorySize, G1_SMEM);
        cudaFuncSetAttribute(gemm2_kernel, cudaFuncAttributeMaxDynamicSharedMemorySize, G2_SMEM);
        attr_done = 1;
    }

    cudaMemsetAsync(out, 0, (size_t)out_size * sizeof(float));
    route_kernel<<<1, 256>>>(idx, wts);

    float *gw, *uw, *dw, *xw;
    cudaGetSymbolAddress((void**)&gw, g_gw);
    cudaGetSymbolAddress((void**)&uw, g_uw);
    cudaGetSymbolAddress((void**)&dw, g_dw);
    cudaGetSymbolAddress((void**)&xw, g_xw);

    const size_t nw = NW;
    const size_t nx = (size_t)T_NUM * H_DIM;
    roundw_kernel<<<dim3((unsigned)(nw / 1024), 3), 256>>>(gate, gw, up, uw, down, dw);
    roundx_kernel<<<(unsigned)(nx / 1024), 256>>>(x, xw, nx);

    gemm1_kernel<<<dim3(T_NUM / TM, I_DIM / TN, E_NUM), NTHREADS, G1_SMEM>>>();
    gemm2_kernel<<<dim3(T_NUM / TM, H_DIM / TN, E_NUM), NTHREADS, G2_SMEM>>>(out);
}